// round 7
// baseline (speedup 1.0000x reference)
#include <cuda_runtime.h>
#include <cstdint>

#define M_MOL 64
#define N_ATM 512
#define RC2 49.0f      // (cutoff + shell)^2 = 7^2
#define I_TILE 4       // smaller blocks -> 8192 blocks -> ~6.9 waves, tiny tail
#define NTHREADS 256

__global__ __launch_bounds__(NTHREADS) void nbl_kernel(
    const float* __restrict__ pos,   // [64, 512, 3]
    float* __restrict__ out)         // [64, 512, 512, 3]
{
    __shared__ float sp[N_ATM * 3];  // this molecule's positions, 6 KB

    const int m = blockIdx.y;
    const float* pm = pos + (size_t)m * N_ATM * 3;

    // cooperative load of the molecule's positions into smem
    for (int t = threadIdx.x; t < N_ATM * 3; t += NTHREADS)
        sp[t] = pm[t];
    __syncthreads();

    const int i0 = blockIdx.x * I_TILE;

    #pragma unroll
    for (int ii = 0; ii < I_TILE; ii++) {
        const int i = i0 + ii;
        // broadcast read of pos_i (all lanes same address -> free)
        const float xi = sp[i * 3 + 0];
        const float yi = sp[i * 3 + 1];
        const float zi = sp[i * 3 + 2];

        float* orow = out + ((size_t)(m * N_ATM + i)) * N_ATM * 3;

        #pragma unroll
        for (int jb = 0; jb < N_ATM / NTHREADS; jb++) {
            const int j = jb * NTHREADS + threadIdx.x;
            // conflict-free: bank(3j+c) mod 32, gcd(3,32)=1
            const float dx = sp[j * 3 + 0] - xi;
            const float dy = sp[j * 3 + 1] - yi;
            const float dz = sp[j * 3 + 2] - zi;
            const float d2 = dx * dx + dy * dy + dz * dz;
            const bool keep = (d2 < RC2) && (j != i);

            // streaming stores: output is write-once, larger than L2
            __stcs(&orow[j * 3 + 0], keep ? dx : 0.0f);
            __stcs(&orow[j * 3 + 1], keep ? dy : 0.0f);
            __stcs(&orow[j * 3 + 2], keep ? dz : 0.0f);
        }
    }
}

extern "C" void kernel_launch(void* const* d_in, const int* in_sizes, int n_in,
                              void* d_out, int out_size)
{
    const float* pos = (const float*)d_in[0];
    float* out = (float*)d_out;

    dim3 grid(N_ATM / I_TILE, M_MOL);   // (128, 64) = 8192 blocks
    nbl_kernel<<<grid, NTHREADS>>>(pos, out);
}

// round 9
// speedup vs baseline: 2.2109x; 2.2109x over previous
#include <cuda_runtime.h>
#include <cstdint>

#define M_MOL 64
#define N_ATM 512
#define RC2 49.0f      // (cutoff + shell)^2 = 7^2
#define I_TILE 8
#define NTHREADS 256   // 8 warps, warp w owns 64 atoms j in [64w, 64w+64)

__global__ __launch_bounds__(NTHREADS) void nbl_kernel(
    const float* __restrict__ pos,   // [64, 512, 3]
    float* __restrict__ out)         // [64, 512, 512, 3]
{
    __shared__ float sp[N_ATM * 3];      // molecule positions, 6 KB
    __shared__ float rowbuf[N_ATM * 3];  // staging: warp-private 768B regions

    const int m = blockIdx.y;
    const float* pm = pos + (size_t)m * N_ATM * 3;

    for (int t = threadIdx.x; t < N_ATM * 3; t += NTHREADS)
        sp[t] = pm[t];
    __syncthreads();

    const int w    = threadIdx.x >> 5;   // warp id, 0..7
    const int lane = threadIdx.x & 31;
    const int i0   = blockIdx.x * I_TILE;

    // warp w's region: output floats [192w, 192w+192) of each row
    float* rb = &rowbuf[192 * w];

    #pragma unroll
    for (int ii = 0; ii < I_TILE; ii++) {
        const int i = i0 + ii;
        const float xi = sp[i * 3 + 0];  // broadcast
        const float yi = sp[i * 3 + 1];
        const float zi = sp[i * 3 + 2];

        // ---- compute phase: stride-3 smem (conflict-free both ways) ----
        #pragma unroll
        for (int jj = 0; jj < 64; jj += 32) {
            const int jl = jj + lane;          // local j in [0,64)
            const int j  = 64 * w + jl;        // global atom index
            const float dx = sp[j * 3 + 0] - xi;
            const float dy = sp[j * 3 + 1] - yi;
            const float dz = sp[j * 3 + 2] - zi;
            const float d2 = dx * dx + dy * dy + dz * dz;
            const bool keep = (d2 < RC2) && (j != i);
            rb[jl * 3 + 0] = keep ? dx : 0.0f;
            rb[jl * 3 + 1] = keep ? dy : 0.0f;
            rb[jl * 3 + 2] = keep ? dz : 0.0f;
        }
        __syncwarp();

        // ---- copy phase: contiguous 256B per warp-instruction ----
        // 192 floats = 96 uint2; lane stride 8B -> full sectors, no partials
        const uint2* rbv = reinterpret_cast<const uint2*>(rb);
        uint2* ov = reinterpret_cast<uint2*>(
            out + ((size_t)(m * N_ATM + i)) * (N_ATM * 3) + 192 * w);
        #pragma unroll
        for (int k = 0; k < 3; k++) {
            const int e = k * 32 + lane;
            __stcs(&ov[e], rbv[e]);
        }
        __syncwarp();   // WAR guard before next i overwrites rowbuf
    }
}

extern "C" void kernel_launch(void* const* d_in, const int* in_sizes, int n_in,
                              void* d_out, int out_size)
{
    const float* pos = (const float*)d_in[0];
    float* out = (float*)d_out;

    dim3 grid(N_ATM / I_TILE, M_MOL);   // (64, 64)
    nbl_kernel<<<grid, NTHREADS>>>(pos, out);
}

// round 14
// speedup vs baseline: 2.2300x; 1.0087x over previous
#include <cuda_runtime.h>
#include <cstdint>

#define M_MOL 64
#define N_ATM 512
#define RC2 49.0f      // (cutoff + shell)^2 = 7^2
#define I_TILE 8
#define NTHREADS 256   // 8 warps = 4 j-quarters x 2 i-halves

__global__ __launch_bounds__(NTHREADS) void nbl_kernel(
    const float* __restrict__ pos,   // [64, 512, 3]
    float* __restrict__ out)         // [64, 512, 512, 3]
{
    __shared__ float sp[N_ATM * 3];        // molecule positions, 6 KB
    __shared__ float rowbuf[N_ATM * 3 * 2];// staging: 8 warps x 1536 B = 12 KB

    const int m = blockIdx.y;
    const float* pm = pos + (size_t)m * N_ATM * 3;

    for (int t = threadIdx.x; t < N_ATM * 3; t += NTHREADS)
        sp[t] = pm[t];
    __syncthreads();

    const int w    = threadIdx.x >> 5;   // warp id, 0..7
    const int lane = threadIdx.x & 31;
    const int jq   = w & 3;              // j-quarter: atoms [128*jq, 128*jq+128)
    const int ih   = w >> 2;             // i-half within the tile
    const int i0   = blockIdx.x * I_TILE + ih * (I_TILE / 2);

    const int jbase = 128 * jq + 4 * lane;       // this lane's 4 consecutive atoms
    // lane's 12 position floats, contiguous, 16B-aligned (byte off = 48*lane)
    const float4* spv = reinterpret_cast<const float4*>(sp + (size_t)jbase * 3);
    float* rb = &rowbuf[384 * w];                // warp-private 1536 B
    float4* rb4w = reinterpret_cast<float4*>(rb) + lane * 3;
    const float4* rbv = reinterpret_cast<const float4*>(rb);

    #pragma unroll
    for (int ii = 0; ii < I_TILE / 2; ii++) {
        const int i = i0 + ii;
        const float xi = sp[i * 3 + 0];  // broadcast
        const float yi = sp[i * 3 + 1];
        const float zi = sp[i * 3 + 2];

        // ---- compute: 3x LDS.128 (48B lane stride, conflict-free) ----
        const float4 p0 = spv[0];        // {x0,y0,z0,x1}
        const float4 p1 = spv[1];        // {y1,z1,x2,y2}
        const float4 p2 = spv[2];        // {z2,x3,y3,z3}

        float4 q0 = make_float4(p0.x - xi, p0.y - yi, p0.z - zi, p0.w - xi);
        float4 q1 = make_float4(p1.x - yi, p1.y - zi, p1.z - xi, p1.w - yi);
        float4 q2 = make_float4(p2.x - zi, p2.y - xi, p2.z - yi, p2.w - zi);

        const float d2_0 = q0.x * q0.x + q0.y * q0.y + q0.z * q0.z;
        const float d2_1 = q0.w * q0.w + q1.x * q1.x + q1.y * q1.y;
        const float d2_2 = q1.z * q1.z + q1.w * q1.w + q2.x * q2.x;
        const float d2_3 = q2.y * q2.y + q2.z * q2.z + q2.w * q2.w;

        if (!((d2_0 < RC2) && (jbase + 0 != i))) { q0.x = 0.f; q0.y = 0.f; q0.z = 0.f; }
        if (!((d2_1 < RC2) && (jbase + 1 != i))) { q0.w = 0.f; q1.x = 0.f; q1.y = 0.f; }
        if (!((d2_2 < RC2) && (jbase + 2 != i))) { q1.z = 0.f; q1.w = 0.f; q2.x = 0.f; }
        if (!((d2_3 < RC2) && (jbase + 3 != i))) { q2.y = 0.f; q2.z = 0.f; q2.w = 0.f; }

        // ---- stage: 3x STS.128 (48B lane stride, conflict-free) ----
        rb4w[0] = q0;
        rb4w[1] = q1;
        rb4w[2] = q2;
        __syncwarp();

        // ---- flush: 3x LDS.128 (16B stride) + 3x STG.128 (512B contiguous/instr) ----
        float4* ov = reinterpret_cast<float4*>(
            out + ((size_t)(m * N_ATM + i)) * (N_ATM * 3) + 384 * jq);
        #pragma unroll
        for (int k = 0; k < 3; k++) {
            const int e = k * 32 + lane;
            __stcs(&ov[e], rbv[e]);
        }
        __syncwarp();   // WAR guard before next i overwrites rowbuf
    }
}

extern "C" void kernel_launch(void* const* d_in, const int* in_sizes, int n_in,
                              void* d_out, int out_size)
{
    const float* pos = (const float*)d_in[0];
    float* out = (float*)d_out;

    dim3 grid(N_ATM / I_TILE, M_MOL);   // (64, 64)
    nbl_kernel<<<grid, NTHREADS>>>(pos, out);
}